// round 15
// baseline (speedup 1.0000x reference)
#include <cuda_runtime.h>
#include <stdint.h>

// GLCMAttention round 15:
//   k1: quarter-image hist (grid 2048), 64KB u8 hist, 3 CTAs/SM, fully
//       unrolled rows, plain-store partials + ticket: 4th finisher per image
//       computes feats+MLP -> g_scale (self-resetting ticket).
//   k2: pure streaming out = x * g_scale[img], __ldcs/__stcs hints.
//
// hist layout (bank == owner-lane for every access):
//   byte addr = warp<<13 | (q*8+qs)<<7 | lane<<2 | angle

#define HIST_BYTES 65536
#define SMEM_TOTAL (HIST_BYTES + 64)

__device__ unsigned g_part[2048 * 256];   // per-quarter partial totals
__device__ float    g_scale[512];
__device__ int      g_ticket[512];        // zero-init; self-resetting

__device__ __forceinline__ unsigned q7(float v) { return (unsigned)(int)(v * 7.0f); }

// Thread t sums counter-id t across all 256 per-thread regions.
__device__ __forceinline__ unsigned flush_hist(const unsigned char* hist,
                                               int t, int lane)
{
    unsigned acc = 0;
    const unsigned sel = 1u << ((t & 3) * 8);          // extract byte 'angle'
    const unsigned pairbase = (unsigned)(t >> 2) << 7; // pair row (128B)
    const unsigned kst = (unsigned)(lane >> 2) & 7u;
    #pragma unroll
    for (int w = 0; w < 8; ++w) {
        unsigned base = ((unsigned)w << 13) | pairbase;
        #pragma unroll
        for (int k = 0; k < 8; ++k) {
            unsigned kk = ((unsigned)k + kst) & 7u;
            uint4 v = *(const uint4*)(hist + base + (kk << 4));
            acc = __dp4a(v.x, sel, acc);
            acc = __dp4a(v.y, sel, acc);
            acc = __dp4a(v.z, sel, acc);
            acc = __dp4a(v.w, sel, acc);
        }
    }
    return acc;
}

// One pixel: 4 angle counters = 4 distinct bytes; loads grouped before stores.
#define PIXEL(QV, A0, A1, A2, A3)                                            \
    {                                                                        \
        unsigned char* b = hb + ((QV) << 10);                                \
        unsigned char* pa = b + ((A0) << 7);                                 \
        unsigned char* pb = b + ((A1) << 7) + 1;                             \
        unsigned char* pc = b + ((A2) << 7) + 2;                             \
        unsigned char* pd = b + ((A3) << 7) + 3;                             \
        unsigned va = *pa, vb = *pb, vc = *pc, vd = *pd;                     \
        *pa = (unsigned char)(va + 1u);                                      \
        *pb = (unsigned char)(vb + 1u);                                      \
        *pc = (unsigned char)(vc + 1u);                                      \
        *pd = (unsigned char)(vd + 1u);                                      \
    }

// Load strip-local row R (8 floats for this lane) or zeros if out of range.
#define LOADROW(D0,D1,D2,D3,D4,D5,D6,D7,R)                                   \
    {                                                                        \
        float4 aa = make_float4(0.f,0.f,0.f,0.f);                            \
        float4 bb = make_float4(0.f,0.f,0.f,0.f);                            \
        if (((R) <= 8) && ((grow + (R)) < 256)) {                            \
            const float4* p = (const float4*)(rowbase + (size_t)(R) * 256);  \
            aa = p[0]; bb = p[1];                                            \
        }                                                                    \
        D0=aa.x; D1=aa.y; D2=aa.z; D3=aa.w;                                  \
        D4=bb.x; D5=bb.y; D6=bb.z; D7=bb.w;                                  \
    }

// Quantize a row + its warp-edge shfls.
#define QUANTROW(S0,S1,S2,S3,S4,S5,S6,S7)                                    \
    t0=q7(S0); t1=q7(S1); t2=q7(S2); t3=q7(S3);                              \
    t4=q7(S4); t5=q7(S5); t6=q7(S6); t7=q7(S7);                              \
    Lt = __shfl_up_sync(0xFFFFFFFFu, t7, 1);   if (lane == 0)  Lt = 0u;      \
    Rt = __shfl_down_sync(0xFFFFFFFFu, t0, 1); if (lane == 31) Rt = 0u;

// Pipeline step: quantize row Y+2, prefetch row Y+4, RMW row Y, rotate.
#define STEP(Y,S0,S1,S2,S3,S4,S5,S6,S7)                                      \
    {                                                                        \
        unsigned t0,t1,t2,t3,t4,t5,t6,t7, Lt, Rt;                            \
        QUANTROW(S0,S1,S2,S3,S4,S5,S6,S7)                                    \
        LOADROW(S0,S1,S2,S3,S4,S5,S6,S7,(Y)+4)                               \
        PIXEL(qc0, Lc,  Ln,  qn0, qn1)                                       \
        PIXEL(qc1, qc0, qn0, qn1, qn2)                                       \
        PIXEL(qc2, qc1, qn1, qn2, qn3)                                       \
        PIXEL(qc3, qc2, qn2, qn3, qn4)                                       \
        PIXEL(qc4, qc3, qn3, qn4, qn5)                                       \
        PIXEL(qc5, qc4, qn4, qn5, qn6)                                       \
        PIXEL(qc6, qc5, qn5, qn6, qn7)                                       \
        PIXEL(qc7, qc6, qn6, qn7, Rn)                                        \
        qc0=qn0; qc1=qn1; qc2=qn2; qc3=qn3;                                  \
        qc4=qn4; qc5=qn5; qc6=qn6; qc7=qn7; Lc=Ln;                           \
        qn0=t0; qn1=t1; qn2=t2; qn3=t3;                                      \
        qn4=t4; qn5=t5; qn6=t6; qn7=t7; Ln=Lt; Rn=Rt;                        \
    }

__global__ void __launch_bounds__(256, 3)
glcm_hist_kernel(const float* __restrict__ x,
                 const float* __restrict__ W1,
                 const float* __restrict__ W2)
{
    extern __shared__ unsigned char smem[];
    unsigned char* hist = smem;

    const int t = threadIdx.x, lane = t & 31, w = t >> 5;
    const int bx  = blockIdx.x;
    const int img = bx >> 2;
    const int qd  = bx & 3;
    const float* xp = x + (size_t)img * 65536;

    // ---- zero hist ----
    uint4* h4 = (uint4*)hist;
    #pragma unroll
    for (int i = 0; i < 16; ++i) h4[t + (i << 8)] = make_uint4(0u,0u,0u,0u);
    __syncthreads();

    unsigned char* hb = hist + (w << 13) + (lane << 2);

    const int grow = (qd << 6) + (w << 3);         // strip's global row 0
    const float* rowbase = xp + grow * 256 + (lane << 3);

    // ---- prologue: rows 0,1 quantized; rows 2,3 prefetched ----
    unsigned qc0,qc1,qc2,qc3,qc4,qc5,qc6,qc7, Lc;
    unsigned qn0,qn1,qn2,qn3,qn4,qn5,qn6,qn7, Ln, Rn;
    float fa0,fa1,fa2,fa3,fa4,fa5,fa6,fa7;
    float fb0,fb1,fb2,fb3,fb4,fb5,fb6,fb7;
    {
        unsigned t0,t1,t2,t3,t4,t5,t6,t7, Lt, Rt;
        LOADROW(fa0,fa1,fa2,fa3,fa4,fa5,fa6,fa7, 0)
        QUANTROW(fa0,fa1,fa2,fa3,fa4,fa5,fa6,fa7)
        qc0=t0; qc1=t1; qc2=t2; qc3=t3; qc4=t4; qc5=t5; qc6=t6; qc7=t7;
        Lc = Lt; (void)Rt;
        LOADROW(fa0,fa1,fa2,fa3,fa4,fa5,fa6,fa7, 1)
        QUANTROW(fa0,fa1,fa2,fa3,fa4,fa5,fa6,fa7)
        qn0=t0; qn1=t1; qn2=t2; qn3=t3; qn4=t4; qn5=t5; qn6=t6; qn7=t7;
        Ln = Lt; Rn = Rt;
    }
    LOADROW(fa0,fa1,fa2,fa3,fa4,fa5,fa6,fa7, 2)
    LOADROW(fb0,fb1,fb2,fb3,fb4,fb5,fb6,fb7, 3)

    // ---- 8 rows, fully unrolled (max 8*8=64 per u8 counter) ----
    STEP(0, fa0,fa1,fa2,fa3,fa4,fa5,fa6,fa7)
    STEP(1, fb0,fb1,fb2,fb3,fb4,fb5,fb6,fb7)
    STEP(2, fa0,fa1,fa2,fa3,fa4,fa5,fa6,fa7)
    STEP(3, fb0,fb1,fb2,fb3,fb4,fb5,fb6,fb7)
    STEP(4, fa0,fa1,fa2,fa3,fa4,fa5,fa6,fa7)
    STEP(5, fb0,fb1,fb2,fb3,fb4,fb5,fb6,fb7)
    STEP(6, fa0,fa1,fa2,fa3,fa4,fa5,fa6,fa7)
    STEP(7, fb0,fb1,fb2,fb3,fb4,fb5,fb6,fb7)

    __syncthreads();
    g_part[bx * 256 + t] = flush_hist(hist, t, lane);

    // ---- ticket: 4th finisher for this image computes feats+MLP ----
    __threadfence();
    __shared__ int win;
    __shared__ float feats[16];
    if (t == 0) {
        int v = atomicAdd(&g_ticket[img], 1);
        win = (v == 3);
        if (v == 3) g_ticket[img] = 0;     // self-reset for graph replays
    }
    __syncthreads();
    if (!win) return;
    __threadfence();                        // acquire partials

    if (t < 32) {
        int angle = t >> 3;
        int sub   = t & 7;
        const float inv = 1.0f / 65536.0f;
        float fi = (float)sub;
        float contrast = 0.f, homog = 0.f, energy = 0.f, corr = 0.f;
        const unsigned* part = g_part + img * 1024;   // 4 quarters x 256
        #pragma unroll
        for (int j = 0; j < 8; ++j) {
            int idx = (((sub << 3) + j) << 2) + angle;
            unsigned cnt = part[idx] + part[256 + idx]
                         + part[512 + idx] + part[768 + idx];
            float p = (float)cnt * inv;
            float d = fi - (float)j;
            contrast += d * d * p;
            homog    += p / (1.0f + fabsf(d));
            energy   += p * p;
            corr     += (fi - 3.5f) * ((float)j - 3.5f) * p;
        }
        #pragma unroll
        for (int off = 4; off; off >>= 1) {
            contrast += __shfl_down_sync(0xFFFFFFFFu, contrast, off);
            homog    += __shfl_down_sync(0xFFFFFFFFu, homog,    off);
            energy   += __shfl_down_sync(0xFFFFFFFFu, energy,   off);
            corr     += __shfl_down_sync(0xFFFFFFFFu, corr,     off);
        }
        if (sub == 0) {
            feats[angle * 4 + 0] = contrast;
            feats[angle * 4 + 1] = homog;
            feats[angle * 4 + 2] = energy;
            feats[angle * 4 + 3] = corr * (1.0f / 6.000001f);  // /(std^2+1e-6)
        }
    }
    __syncthreads();

    if (t < 16) {
        float h = 0.f;
        #pragma unroll
        for (int f = 0; f < 16; ++f) h += feats[f] * W1[f * 16 + t];
        h = fmaxf(h, 0.0f);
        int c = img & 63;
        float v = h * W2[t * 64 + c];
        #pragma unroll
        for (int off = 8; off; off >>= 1)
            v += __shfl_down_sync(0x0000FFFFu, v, off);
        if (t == 0)
            g_scale[img] = 1.0f + 1.0f / (1.0f + expf(-v));
    }
}

// k2: pure streaming scale with no-allocate cache hints.
__global__ void __launch_bounds__(256)
glcm_scale_kernel(const float* __restrict__ x, float* __restrict__ out)
{
    const int blk = blockIdx.x;
    const float s = g_scale[blk >> 2];
    const float4* xs = (const float4*)x + (size_t)blk * 4096;
    float4*       os = (float4*)out     + (size_t)blk * 4096;
    const int t = threadIdx.x;
    #pragma unroll
    for (int k = 0; k < 16; ++k) {
        int i = t + (k << 8);
        float4 v = __ldcs(&xs[i]);
        v.x *= s; v.y *= s; v.z *= s; v.w *= s;
        __stcs(&os[i], v);
    }
}

extern "C" void kernel_launch(void* const* d_in, const int* in_sizes, int n_in,
                              void* d_out, int out_size)
{
    (void)in_sizes; (void)n_in; (void)out_size;
    const float* x  = (const float*)d_in[0];
    const float* W1 = (const float*)d_in[1];
    const float* W2 = (const float*)d_in[2];
    float* out = (float*)d_out;

    cudaFuncSetAttribute(glcm_hist_kernel,
                         cudaFuncAttributeMaxDynamicSharedMemorySize, SMEM_TOTAL);
    glcm_hist_kernel<<<2048, 256, SMEM_TOTAL>>>(x, W1, W2);
    glcm_scale_kernel<<<2048, 256>>>(x, out);
}

// round 16
// speedup vs baseline: 1.1343x; 1.1343x over previous
#include <cuda_runtime.h>
#include <stdint.h>

// GLCMAttention round 16: single fused pipelined kernel.
//   Blocks 0..2047: hist quarter of img=b>>2 (R14 loop, 64KB u8 hist,
//     3 CTAs/SM) -> partials -> ticket winner computes g_scale[img]
//     (value==ready flag) -> then STREAM quarter of img-112 (spin on its
//     scale; strictly-backward dependency => deadlock-free).
//   Blocks 2048..2495: stream quarters of images 400..511.
// Overlaps DRAM-bound streaming with smem-bound hist.
//
// hist layout (bank == owner-lane for every access):
//   byte addr = warp<<13 | (q*8+qs)<<7 | lane<<2 | angle

#define HIST_BYTES 65536
#define SMEM_TOTAL (HIST_BYTES + 64)
#define PIPE_D 112

__device__ unsigned g_part[2048 * 256];   // per-quarter partial totals
__device__ float    g_scale[512];         // 0 = not ready; value in (1,2)
__device__ int      g_ticket[512];        // zero-init; self-resetting

__device__ __forceinline__ unsigned q7(float v) { return (unsigned)(int)(v * 7.0f); }

// Thread t sums counter-id t across all 256 per-thread regions.
__device__ __forceinline__ unsigned flush_hist(const unsigned char* hist,
                                               int t, int lane)
{
    unsigned acc = 0;
    const unsigned sel = 1u << ((t & 3) * 8);          // extract byte 'angle'
    const unsigned pairbase = (unsigned)(t >> 2) << 7; // pair row (128B)
    const unsigned kst = (unsigned)(lane >> 2) & 7u;
    #pragma unroll
    for (int w = 0; w < 8; ++w) {
        unsigned base = ((unsigned)w << 13) | pairbase;
        #pragma unroll
        for (int k = 0; k < 8; ++k) {
            unsigned kk = ((unsigned)k + kst) & 7u;
            uint4 v = *(const uint4*)(hist + base + (kk << 4));
            acc = __dp4a(v.x, sel, acc);
            acc = __dp4a(v.y, sel, acc);
            acc = __dp4a(v.z, sel, acc);
            acc = __dp4a(v.w, sel, acc);
        }
    }
    return acc;
}

// One pixel: 4 angle counters = 4 distinct bytes; loads grouped before stores.
#define PIXEL(QV, A0, A1, A2, A3)                                            \
    {                                                                        \
        unsigned char* b = hb + ((QV) << 10);                                \
        unsigned char* pa = b + ((A0) << 7);                                 \
        unsigned char* pb = b + ((A1) << 7) + 1;                             \
        unsigned char* pc = b + ((A2) << 7) + 2;                             \
        unsigned char* pd = b + ((A3) << 7) + 3;                             \
        unsigned va = *pa, vb = *pb, vc = *pc, vd = *pd;                     \
        *pa = (unsigned char)(va + 1u);                                      \
        *pb = (unsigned char)(vb + 1u);                                      \
        *pc = (unsigned char)(vc + 1u);                                      \
        *pd = (unsigned char)(vd + 1u);                                      \
    }

// Load strip-local row R (8 floats for this lane) or zeros if out of range.
#define LOADROW(D0,D1,D2,D3,D4,D5,D6,D7,R)                                   \
    {                                                                        \
        float4 aa = make_float4(0.f,0.f,0.f,0.f);                            \
        float4 bb = make_float4(0.f,0.f,0.f,0.f);                            \
        if (((R) <= 8) && ((grow + (R)) < 256)) {                            \
            const float4* p = (const float4*)(rowbase + (size_t)(R) * 256);  \
            aa = p[0]; bb = p[1];                                            \
        }                                                                    \
        D0=aa.x; D1=aa.y; D2=aa.z; D3=aa.w;                                  \
        D4=bb.x; D5=bb.y; D6=bb.z; D7=bb.w;                                  \
    }

// Quantize a row + its warp-edge shfls.
#define QUANTROW(S0,S1,S2,S3,S4,S5,S6,S7)                                    \
    t0=q7(S0); t1=q7(S1); t2=q7(S2); t3=q7(S3);                              \
    t4=q7(S4); t5=q7(S5); t6=q7(S6); t7=q7(S7);                              \
    Lt = __shfl_up_sync(0xFFFFFFFFu, t7, 1);   if (lane == 0)  Lt = 0u;      \
    Rt = __shfl_down_sync(0xFFFFFFFFu, t0, 1); if (lane == 31) Rt = 0u;

// Pipeline step: quantize row Y+2, prefetch row Y+4, RMW row Y, rotate.
#define STEP(Y,S0,S1,S2,S3,S4,S5,S6,S7)                                      \
    {                                                                        \
        unsigned t0,t1,t2,t3,t4,t5,t6,t7, Lt, Rt;                            \
        QUANTROW(S0,S1,S2,S3,S4,S5,S6,S7)                                    \
        LOADROW(S0,S1,S2,S3,S4,S5,S6,S7,(Y)+4)                               \
        PIXEL(qc0, Lc,  Ln,  qn0, qn1)                                       \
        PIXEL(qc1, qc0, qn0, qn1, qn2)                                       \
        PIXEL(qc2, qc1, qn1, qn2, qn3)                                       \
        PIXEL(qc3, qc2, qn2, qn3, qn4)                                       \
        PIXEL(qc4, qc3, qn3, qn4, qn5)                                       \
        PIXEL(qc5, qc4, qn4, qn5, qn6)                                       \
        PIXEL(qc6, qc5, qn5, qn6, qn7)                                       \
        PIXEL(qc7, qc6, qn6, qn7, Rn)                                        \
        qc0=qn0; qc1=qn1; qc2=qn2; qc3=qn3;                                  \
        qc4=qn4; qc5=qn5; qc6=qn6; qc7=qn7; Lc=Ln;                           \
        qn0=t0; qn1=t1; qn2=t2; qn3=t3;                                      \
        qn4=t4; qn5=t5; qn6=t6; qn7=t7; Ln=Lt; Rn=Rt;                        \
    }

__global__ void __launch_bounds__(256, 3)
glcm_fused_kernel(const float* __restrict__ x,
                  const float* __restrict__ W1,
                  const float* __restrict__ W2,
                  float* __restrict__ out)
{
    extern __shared__ unsigned char smem[];
    unsigned char* hist = smem;

    const int t = threadIdx.x, lane = t & 31, w = t >> 5;
    const int bx = blockIdx.x;

    int simg, sqd;                          // streaming assignment

    if (bx < 2048) {
        const int img = bx >> 2;
        const int qd  = bx & 3;
        simg = img - PIPE_D; sqd = qd;
        const float* xp = x + (size_t)img * 65536;

        // ---- zero hist ----
        uint4* h4 = (uint4*)hist;
        #pragma unroll
        for (int i = 0; i < 16; ++i) h4[t + (i << 8)] = make_uint4(0u,0u,0u,0u);
        __syncthreads();

        unsigned char* hb = hist + (w << 13) + (lane << 2);

        const int grow = (qd << 6) + (w << 3);
        const float* rowbase = xp + grow * 256 + (lane << 3);

        // ---- prologue ----
        unsigned qc0,qc1,qc2,qc3,qc4,qc5,qc6,qc7, Lc;
        unsigned qn0,qn1,qn2,qn3,qn4,qn5,qn6,qn7, Ln, Rn;
        float fa0,fa1,fa2,fa3,fa4,fa5,fa6,fa7;
        float fb0,fb1,fb2,fb3,fb4,fb5,fb6,fb7;
        {
            unsigned t0,t1,t2,t3,t4,t5,t6,t7, Lt, Rt;
            LOADROW(fa0,fa1,fa2,fa3,fa4,fa5,fa6,fa7, 0)
            QUANTROW(fa0,fa1,fa2,fa3,fa4,fa5,fa6,fa7)
            qc0=t0; qc1=t1; qc2=t2; qc3=t3; qc4=t4; qc5=t5; qc6=t6; qc7=t7;
            Lc = Lt; (void)Rt;
            LOADROW(fa0,fa1,fa2,fa3,fa4,fa5,fa6,fa7, 1)
            QUANTROW(fa0,fa1,fa2,fa3,fa4,fa5,fa6,fa7)
            qn0=t0; qn1=t1; qn2=t2; qn3=t3; qn4=t4; qn5=t5; qn6=t6; qn7=t7;
            Ln = Lt; Rn = Rt;
        }
        LOADROW(fa0,fa1,fa2,fa3,fa4,fa5,fa6,fa7, 2)
        LOADROW(fb0,fb1,fb2,fb3,fb4,fb5,fb6,fb7, 3)

        // ---- 8 rows (max 64 per u8 counter) ----
        #pragma unroll 2
        for (int y = 0; y < 8; y += 2) {
            STEP(y,   fa0,fa1,fa2,fa3,fa4,fa5,fa6,fa7)
            STEP(y+1, fb0,fb1,fb2,fb3,fb4,fb5,fb6,fb7)
        }

        __syncthreads();
        g_part[bx * 256 + t] = flush_hist(hist, t, lane);

        // ---- ticket: 4th finisher computes feats+MLP -> g_scale[img] ----
        __threadfence();
        __shared__ int win;
        __shared__ float feats[16];
        if (t == 0) {
            int v = atomicAdd(&g_ticket[img], 1);
            win = (v == 3);
            if (v == 3) g_ticket[img] = 0;      // self-reset for replays
        }
        __syncthreads();
        if (win) {
            __threadfence();                    // acquire partials
            if (t < 32) {
                int angle = t >> 3;
                int sub   = t & 7;
                const float inv = 1.0f / 65536.0f;
                float fi = (float)sub;
                float contrast = 0.f, homog = 0.f, energy = 0.f, corr = 0.f;
                const unsigned* part = g_part + img * 1024;
                #pragma unroll
                for (int j = 0; j < 8; ++j) {
                    int idx = (((sub << 3) + j) << 2) + angle;
                    unsigned cnt = part[idx] + part[256 + idx]
                                 + part[512 + idx] + part[768 + idx];
                    float p = (float)cnt * inv;
                    float d = fi - (float)j;
                    contrast += d * d * p;
                    homog    += p / (1.0f + fabsf(d));
                    energy   += p * p;
                    corr     += (fi - 3.5f) * ((float)j - 3.5f) * p;
                }
                #pragma unroll
                for (int off = 4; off; off >>= 1) {
                    contrast += __shfl_down_sync(0xFFFFFFFFu, contrast, off);
                    homog    += __shfl_down_sync(0xFFFFFFFFu, homog,    off);
                    energy   += __shfl_down_sync(0xFFFFFFFFu, energy,   off);
                    corr     += __shfl_down_sync(0xFFFFFFFFu, corr,     off);
                }
                if (sub == 0) {
                    feats[angle * 4 + 0] = contrast;
                    feats[angle * 4 + 1] = homog;
                    feats[angle * 4 + 2] = energy;
                    feats[angle * 4 + 3] = corr * (1.0f / 6.000001f);
                }
            }
            __syncthreads();
            if (t < 16) {
                float h = 0.f;
                #pragma unroll
                for (int f = 0; f < 16; ++f) h += feats[f] * W1[f * 16 + t];
                h = fmaxf(h, 0.0f);
                int c = img & 63;
                float v = h * W2[t * 64 + c];
                #pragma unroll
                for (int off = 8; off; off >>= 1)
                    v += __shfl_down_sync(0x0000FFFFu, v, off);
                if (t == 0)
                    g_scale[img] = 1.0f + 1.0f / (1.0f + expf(-v));
                    // plain store: value IS the ready flag (always > 1)
            }
        }
        if (simg < 0) return;                   // images 0..111: hist only
    } else {
        simg = 400 + ((bx - 2048) >> 2);        // tail: images 400..511
        sqd  = bx & 3;
    }

    // ---- stream quarter (simg, sqd): wait for scale, then out = x*s ----
    if (t == 0) {
        while (*(volatile float*)&g_scale[simg] == 0.0f) __nanosleep(64);
    }
    __syncthreads();
    const float s = g_scale[simg];

    const int blk = (simg << 2) + sqd;
    const float4* xs = (const float4*)x + (size_t)blk * 4096;
    float4*       os = (float4*)out     + (size_t)blk * 4096;
    #pragma unroll
    for (int k = 0; k < 16; ++k) {
        int i = t + (k << 8);
        float4 v = xs[i];
        v.x *= s; v.y *= s; v.z *= s; v.w *= s;
        os[i] = v;
    }
}

extern "C" void kernel_launch(void* const* d_in, const int* in_sizes, int n_in,
                              void* d_out, int out_size)
{
    (void)in_sizes; (void)n_in; (void)out_size;
    const float* x  = (const float*)d_in[0];
    const float* W1 = (const float*)d_in[1];
    const float* W2 = (const float*)d_in[2];
    float* out = (float*)d_out;

    cudaFuncSetAttribute(glcm_fused_kernel,
                         cudaFuncAttributeMaxDynamicSharedMemorySize, SMEM_TOTAL);
    glcm_fused_kernel<<<2048 + 4 * PIPE_D, 256, SMEM_TOTAL>>>(x, W1, W2, out);
}